// round 3
// baseline (speedup 1.0000x reference)
#include <cuda_runtime.h>

// Problem constants
#define B_   8
#define NX_  512
#define NR_  512
#define D_   256
#define H_   256

// Scratch (device globals — no allocation allowed in kernel_launch)
__device__ float g_hX[B_ * NX_ * H_];        // [b][x][h]
__device__ float g_hR[B_ * NR_ * H_];        // [b][r][h]
__device__ float g_S [B_ * NR_ * NX_];       // [b][r][x]  (scores, then attn in-place)

__device__ __forceinline__ float fast_tanh(float x) {
    float y;
    asm("tanh.approx.f32 %0, %1;" : "=f"(y) : "f"(x));
    return y;
}

// ---------------------------------------------------------------------------
// Phase 1: hX = X @ W_X^T + b_X   (and hR likewise)
// C[m,n] = sum_k A[m,k] * W[n,k] + bias[n]
// M = 4096, N = H_ = 256, K = D_ = 256.  64x64 tile, 32 k-chunk, 256 thr, 4x4/thr.
// ---------------------------------------------------------------------------
__global__ __launch_bounds__(256) void proj_kernel(const float* __restrict__ A,
                                                   const float* __restrict__ W,
                                                   const float* __restrict__ bias,
                                                   int which) {
    __shared__ float As[32][64];   // [k][m]
    __shared__ float Ws[32][64];   // [k][n]
    float* C = which ? g_hR : g_hX;
    const int K = D_;
    const int N = H_;
    int tid = threadIdx.x;
    int tx = tid & 15, ty = tid >> 4;
    int m0 = blockIdx.y * 64, n0 = blockIdx.x * 64;

    float acc[4][4] = {};

    for (int k0 = 0; k0 < K; k0 += 32) {
#pragma unroll
        for (int l = 0; l < 2; l++) {
            int f = tid + l * 256;
            int row = f >> 3, c4 = f & 7;
            float4 v = *reinterpret_cast<const float4*>(&A[(size_t)(m0 + row) * K + k0 + c4 * 4]);
            As[c4 * 4 + 0][row] = v.x; As[c4 * 4 + 1][row] = v.y;
            As[c4 * 4 + 2][row] = v.z; As[c4 * 4 + 3][row] = v.w;
            float4 w = *reinterpret_cast<const float4*>(&W[(size_t)(n0 + row) * K + k0 + c4 * 4]);
            Ws[c4 * 4 + 0][row] = w.x; Ws[c4 * 4 + 1][row] = w.y;
            Ws[c4 * 4 + 2][row] = w.z; Ws[c4 * 4 + 3][row] = w.w;
        }
        __syncthreads();
#pragma unroll
        for (int k = 0; k < 32; k++) {
            float4 a4 = *reinterpret_cast<const float4*>(&As[k][ty * 4]);
            float4 b4 = *reinterpret_cast<const float4*>(&Ws[k][tx * 4]);
            float a[4] = {a4.x, a4.y, a4.z, a4.w};
            float bb[4] = {b4.x, b4.y, b4.z, b4.w};
#pragma unroll
            for (int i = 0; i < 4; i++)
#pragma unroll
                for (int j = 0; j < 4; j++)
                    acc[i][j] += a[i] * bb[j];
        }
        __syncthreads();
    }

    float4 bv = *reinterpret_cast<const float4*>(&bias[n0 + tx * 4]);
    float bb[4] = {bv.x, bv.y, bv.z, bv.w};
#pragma unroll
    for (int i = 0; i < 4; i++) {
        float4 o;
        o.x = acc[i][0] + bb[0]; o.y = acc[i][1] + bb[1];
        o.z = acc[i][2] + bb[2]; o.w = acc[i][3] + bb[3];
        *reinterpret_cast<float4*>(&C[(size_t)(m0 + ty * 4 + i) * N + n0 + tx * 4]) = o;
    }
}

// ---------------------------------------------------------------------------
// Phase 2: S[b][r][x] = sum_h v_w[h] * tanh(hX[b,x,h] + hR[b,r,h])
// (v_b and per-score constants are dropped: softmax over x is shift-invariant)
// 64(r) x 64(x) tile per block, h-chunks of 32. MUFU(tanh)-bound by design.
// ---------------------------------------------------------------------------
__global__ __launch_bounds__(256) void score_kernel(const float* __restrict__ vw) {
    __shared__ float sX[32][64];   // [h][x]
    __shared__ float sR[32][64];   // [h][r]
    __shared__ float sv[32];
    int tid = threadIdx.x;
    int tx = tid & 15, ty = tid >> 4;
    int x0 = blockIdx.x * 64, r0 = blockIdx.y * 64, b = blockIdx.z;
    const float* hXb = g_hX + (size_t)b * NX_ * H_;
    const float* hRb = g_hR + (size_t)b * NR_ * H_;

    float acc[4][4] = {};

    for (int h0 = 0; h0 < H_; h0 += 32) {
#pragma unroll
        for (int l = 0; l < 2; l++) {
            int f = tid + l * 256;
            int row = f >> 3, c4 = f & 7;
            float4 v = *reinterpret_cast<const float4*>(&hXb[(size_t)(x0 + row) * H_ + h0 + c4 * 4]);
            sX[c4 * 4 + 0][row] = v.x; sX[c4 * 4 + 1][row] = v.y;
            sX[c4 * 4 + 2][row] = v.z; sX[c4 * 4 + 3][row] = v.w;
            float4 w = *reinterpret_cast<const float4*>(&hRb[(size_t)(r0 + row) * H_ + h0 + c4 * 4]);
            sR[c4 * 4 + 0][row] = w.x; sR[c4 * 4 + 1][row] = w.y;
            sR[c4 * 4 + 2][row] = w.z; sR[c4 * 4 + 3][row] = w.w;
        }
        if (tid < 32) sv[tid] = vw[h0 + tid];
        __syncthreads();

#pragma unroll 8
        for (int h = 0; h < 32; h++) {
            float vv = sv[h];
            float4 xv = *reinterpret_cast<const float4*>(&sX[h][tx * 4]);
            float4 rv = *reinterpret_cast<const float4*>(&sR[h][ty * 4]);
            float xs[4] = {xv.x, xv.y, xv.z, xv.w};
            float rs[4] = {rv.x, rv.y, rv.z, rv.w};
#pragma unroll
            for (int i = 0; i < 4; i++)
#pragma unroll
                for (int j = 0; j < 4; j++)
                    acc[i][j] += vv * fast_tanh(rs[i] + xs[j]);
        }
        __syncthreads();
    }

    float* Sb = g_S + (size_t)b * NR_ * NX_;
#pragma unroll
    for (int i = 0; i < 4; i++) {
        float4 o = {acc[i][0], acc[i][1], acc[i][2], acc[i][3]};
        *reinterpret_cast<float4*>(&Sb[(size_t)(r0 + ty * 4 + i) * NX_ + x0 + tx * 4]) = o;
    }
}

// ---------------------------------------------------------------------------
// Phase 3: row-wise softmax over the 512 x-values of each S[b][r][:] (in place)
// One block (128 threads, 4 elems/thread) per row.
// ---------------------------------------------------------------------------
__global__ __launch_bounds__(128) void softmax512_kernel() {
    int row = blockIdx.x;
    float* p = g_S + (size_t)row * NX_;
    int t = threadIdx.x;
    int w = t >> 5, lane = t & 31;

    float4 v = *reinterpret_cast<float4*>(&p[t * 4]);

    float m = fmaxf(fmaxf(v.x, v.y), fmaxf(v.z, v.w));
#pragma unroll
    for (int o = 16; o > 0; o >>= 1) m = fmaxf(m, __shfl_xor_sync(0xffffffffu, m, o));
    __shared__ float sm[4];
    if (lane == 0) sm[w] = m;
    __syncthreads();
    m = fmaxf(fmaxf(sm[0], sm[1]), fmaxf(sm[2], sm[3]));

    v.x = __expf(v.x - m); v.y = __expf(v.y - m);
    v.z = __expf(v.z - m); v.w = __expf(v.w - m);
    float s = v.x + v.y + v.z + v.w;
#pragma unroll
    for (int o = 16; o > 0; o >>= 1) s += __shfl_xor_sync(0xffffffffu, s, o);
    __shared__ float ss[4];
    if (lane == 0) ss[w] = s;
    __syncthreads();
    s = ss[0] + ss[1] + ss[2] + ss[3];

    float inv = 1.0f / s;
    v.x *= inv; v.y *= inv; v.z *= inv; v.w *= inv;
    *reinterpret_cast<float4*>(&p[t * 4]) = v;
}

// ---------------------------------------------------------------------------
// Phase 4: out[b][r][d] = sum_x attn[b][r][x] * X[b][x][d]
// A = g_S[b] (512x512 row-major), Bm = X[b] (512x256 row-major). NN GEMM.
// ---------------------------------------------------------------------------
__global__ __launch_bounds__(256) void out_gemm_kernel(const float* __restrict__ X,
                                                       float* __restrict__ out) {
    __shared__ float As[32][64];   // [k][m]
    __shared__ float Bs[32][64];   // [k][n]
    int tid = threadIdx.x;
    int tx = tid & 15, ty = tid >> 4;
    int n0 = blockIdx.x * 64, m0 = blockIdx.y * 64, b = blockIdx.z;
    const float* Ab = g_S + (size_t)b * NR_ * NX_;
    const float* Xb = X + (size_t)b * NX_ * D_;

    float acc[4][4] = {};

    for (int k0 = 0; k0 < NX_; k0 += 32) {
#pragma unroll
        for (int l = 0; l < 2; l++) {
            int f = tid + l * 256;
            int row = f >> 3, c4 = f & 7;
            float4 v = *reinterpret_cast<const float4*>(&Ab[(size_t)(m0 + row) * NX_ + k0 + c4 * 4]);
            As[c4 * 4 + 0][row] = v.x; As[c4 * 4 + 1][row] = v.y;
            As[c4 * 4 + 2][row] = v.z; As[c4 * 4 + 3][row] = v.w;
        }
#pragma unroll
        for (int l = 0; l < 2; l++) {
            int f = tid + l * 256;
            int row = f >> 4, c4 = f & 15;
            float4 v = *reinterpret_cast<const float4*>(&Xb[(size_t)(k0 + row) * D_ + n0 + c4 * 4]);
            *reinterpret_cast<float4*>(&Bs[row][c4 * 4]) = v;
        }
        __syncthreads();
#pragma unroll
        for (int k = 0; k < 32; k++) {
            float4 a4 = *reinterpret_cast<const float4*>(&As[k][ty * 4]);
            float4 b4 = *reinterpret_cast<const float4*>(&Bs[k][tx * 4]);
            float a[4] = {a4.x, a4.y, a4.z, a4.w};
            float bb[4] = {b4.x, b4.y, b4.z, b4.w};
#pragma unroll
            for (int i = 0; i < 4; i++)
#pragma unroll
                for (int j = 0; j < 4; j++)
                    acc[i][j] += a[i] * bb[j];
        }
        __syncthreads();
    }

#pragma unroll
    for (int i = 0; i < 4; i++) {
        float4 o = {acc[i][0], acc[i][1], acc[i][2], acc[i][3]};
        *reinterpret_cast<float4*>(&out[((size_t)b * NR_ + m0 + ty * 4 + i) * D_ + n0 + tx * 4]) = o;
    }
}

// ---------------------------------------------------------------------------
// Launch: 5 sequential kernels on the default stream (graph-capturable,
// allocation-free; scratch is in __device__ globals).
// Input order per metadata: X, ref, W_X, b_X, W_ref, b_ref, v_w, v_b.
// v_b is provably dropped (softmax shift invariance along x).
// ---------------------------------------------------------------------------
extern "C" void kernel_launch(void* const* d_in, const int* in_sizes, int n_in,
                              void* d_out, int out_size) {
    const float* X     = (const float*)d_in[0];
    const float* ref   = (const float*)d_in[1];
    const float* W_X   = (const float*)d_in[2];
    const float* b_X   = (const float*)d_in[3];
    const float* W_ref = (const float*)d_in[4];
    const float* b_ref = (const float*)d_in[5];
    const float* v_w   = (const float*)d_in[6];
    float* out = (float*)d_out;

    dim3 blk(256);
    proj_kernel<<<dim3(H_ / 64, (B_ * NX_) / 64), blk>>>(X,   W_X,   b_X,   0);
    proj_kernel<<<dim3(H_ / 64, (B_ * NR_) / 64), blk>>>(ref, W_ref, b_ref, 1);
    score_kernel<<<dim3(NX_ / 64, NR_ / 64, B_), blk>>>(v_w);
    softmax512_kernel<<<B_ * NR_, 128>>>();
    out_gemm_kernel<<<dim3(D_ / 64, NR_ / 64, B_), blk>>>(X, out);
}

// round 5
// speedup vs baseline: 1.0479x; 1.0479x over previous
#include <cuda_runtime.h>
#include <cuda_fp16.h>

// Problem constants
#define B_   8
#define NX_  512
#define NR_  512
#define D_   256
#define H_   256

// Scratch (device globals — no allocation allowed anywhere)
__device__ __half g_hXT[B_ * H_ * NX_];   // [b][h][x]  fp16, transposed
__device__ __half g_hRT[B_ * H_ * NR_];   // [b][h][r]  fp16, transposed
__device__ float  g_S  [B_ * NR_ * NX_];  // [b][r][x]  scores -> attn in place

__device__ __forceinline__ __half2 tanh2(__half2 x) {
    __half2 y;
    asm("tanh.approx.f16x2 %0, %1;"
        : "=r"(*reinterpret_cast<unsigned*>(&y))
        : "r"(*reinterpret_cast<unsigned*>(&x)));
    return y;
}

// ---------------------------------------------------------------------------
// Phase 1: hT[b][h][x] = sum_d W[h][d] * A[b][x][d] + bias[h], stored fp16.
// M-dim = h (64-tile), N-dim = x (64-tile), K = D, fp32 compute.
// ---------------------------------------------------------------------------
__global__ __launch_bounds__(256) void proj_kernel(const float* __restrict__ A,
                                                   const float* __restrict__ W,
                                                   const float* __restrict__ bias,
                                                   int which) {
    __shared__ float Ws[32][64];   // [k][h]
    __shared__ float As[32][64];   // [k][x]
    __half* C = which ? g_hRT : g_hXT;
    const int K = D_;
    int tid = threadIdx.x;
    int tx = tid & 15, ty = tid >> 4;
    int x0 = blockIdx.x * 64, h0 = blockIdx.y * 64, b = blockIdx.z;
    const float* Ab = A + (size_t)b * NX_ * D_;   // NX_ == NR_

    float acc[4][4] = {};

    for (int k0 = 0; k0 < K; k0 += 32) {
#pragma unroll
        for (int l = 0; l < 2; l++) {
            int f = tid + l * 256;
            int row = f >> 3, c4 = f & 7;
            float4 w = *reinterpret_cast<const float4*>(&W[(size_t)(h0 + row) * K + k0 + c4 * 4]);
            Ws[c4 * 4 + 0][row] = w.x; Ws[c4 * 4 + 1][row] = w.y;
            Ws[c4 * 4 + 2][row] = w.z; Ws[c4 * 4 + 3][row] = w.w;
            float4 v = *reinterpret_cast<const float4*>(&Ab[(size_t)(x0 + row) * K + k0 + c4 * 4]);
            As[c4 * 4 + 0][row] = v.x; As[c4 * 4 + 1][row] = v.y;
            As[c4 * 4 + 2][row] = v.z; As[c4 * 4 + 3][row] = v.w;
        }
        __syncthreads();
#pragma unroll
        for (int k = 0; k < 32; k++) {
            float4 a4 = *reinterpret_cast<const float4*>(&Ws[k][ty * 4]);   // h
            float4 b4 = *reinterpret_cast<const float4*>(&As[k][tx * 4]);   // x
            float a[4] = {a4.x, a4.y, a4.z, a4.w};
            float bb[4] = {b4.x, b4.y, b4.z, b4.w};
#pragma unroll
            for (int i = 0; i < 4; i++)
#pragma unroll
                for (int j = 0; j < 4; j++)
                    acc[i][j] += a[i] * bb[j];
        }
        __syncthreads();
    }

#pragma unroll
    for (int i = 0; i < 4; i++) {
        int h = h0 + ty * 4 + i;
        float bb = bias[h];
        __half2 p0 = __floats2half2_rn(acc[i][0] + bb, acc[i][1] + bb);
        __half2 p1 = __floats2half2_rn(acc[i][2] + bb, acc[i][3] + bb);
        uint2 pk = {*reinterpret_cast<unsigned*>(&p0), *reinterpret_cast<unsigned*>(&p1)};
        *reinterpret_cast<uint2*>(&C[((size_t)b * H_ + h) * NX_ + x0 + tx * 4]) = pk;
    }
}

// ---------------------------------------------------------------------------
// Phase 2: S[b][r][x] = sum_h v[h] * tanh(hX[b][h][x] + hR[b][h][r])
// f16x2 tanh pairs along x (halves MUFU count), HFMA2 accumulation in half2
// over 8-h chunks, flushed into fp32 accumulators (F2F count reduced 8x).
// v_b / constants dropped (softmax shift-invariant along x).
// ---------------------------------------------------------------------------
__global__ __launch_bounds__(256) void score_kernel(const float* __restrict__ vw) {
    __shared__ __half  sX[32][64];   // [h][x]
    __shared__ __half  sR[32][64];   // [h][r]
    __shared__ __half2 sv2[32];      // v[h] broadcast pair
    int tid = threadIdx.x;
    int tx = tid & 15, ty = tid >> 4;
    int x0 = blockIdx.x * 64, r0 = blockIdx.y * 64, b = blockIdx.z;
    const __half* hXb = g_hXT + (size_t)b * H_ * NX_;
    const __half* hRb = g_hRT + (size_t)b * H_ * NR_;

    float acc[4][4] = {};

    for (int h0 = 0; h0 < H_; h0 += 32) {
        {
            int row = tid >> 3, seg = tid & 7;
            *reinterpret_cast<uint4*>(&sX[row][seg * 8]) =
                *reinterpret_cast<const uint4*>(&hXb[(size_t)(h0 + row) * NX_ + x0 + seg * 8]);
            *reinterpret_cast<uint4*>(&sR[row][seg * 8]) =
                *reinterpret_cast<const uint4*>(&hRb[(size_t)(h0 + row) * NR_ + r0 + seg * 8]);
            if (tid < 32) sv2[tid] = __half2half2(__float2half_rn(vw[h0 + tid]));
        }
        __syncthreads();

#pragma unroll
        for (int hh = 0; hh < 32; hh += 8) {
            __half2 acc2[4][2] = {};
#pragma unroll
            for (int h = 0; h < 8; h++) {
                int hc = hh + h;
                __half2 v2 = sv2[hc];
                uint2 xu = *reinterpret_cast<const uint2*>(&sX[hc][tx * 4]);
                uint2 ru = *reinterpret_cast<const uint2*>(&sR[hc][ty * 4]);
                __half2 x2[2] = {*reinterpret_cast<__half2*>(&xu.x),
                                 *reinterpret_cast<__half2*>(&xu.y)};
                __half2 ra = *reinterpret_cast<__half2*>(&ru.x);
                __half2 rb = *reinterpret_cast<__half2*>(&ru.y);
                __half2 r2[4] = {__half2half2(__low2half(ra)), __half2half2(__high2half(ra)),
                                 __half2half2(__low2half(rb)), __half2half2(__high2half(rb))};
#pragma unroll
                for (int i = 0; i < 4; i++)
#pragma unroll
                    for (int j2 = 0; j2 < 2; j2++) {
                        __half2 t = tanh2(__hadd2(r2[i], x2[j2]));
                        acc2[i][j2] = __hfma2(v2, t, acc2[i][j2]);
                    }
            }
            // flush half2 partials into fp32 accumulators
#pragma unroll
            for (int i = 0; i < 4; i++)
#pragma unroll
                for (int j2 = 0; j2 < 2; j2++) {
                    float2 f = __half22float2(acc2[i][j2]);
                    acc[i][2 * j2 + 0] += f.x;
                    acc[i][2 * j2 + 1] += f.y;
                }
        }
        __syncthreads();
    }

    float* Sb = g_S + (size_t)b * NR_ * NX_;
#pragma unroll
    for (int i = 0; i < 4; i++) {
        float4 o = {acc[i][0], acc[i][1], acc[i][2], acc[i][3]};
        *reinterpret_cast<float4*>(&Sb[(size_t)(r0 + ty * 4 + i) * NX_ + x0 + tx * 4]) = o;
    }
}

// ---------------------------------------------------------------------------
// Phase 3: row-wise softmax over 512 x-values of each S[b][r][:] (in place)
// ---------------------------------------------------------------------------
__global__ __launch_bounds__(128) void softmax512_kernel() {
    int row = blockIdx.x;
    float* p = g_S + (size_t)row * NX_;
    int t = threadIdx.x;
    int w = t >> 5, lane = t & 31;

    float4 v = *reinterpret_cast<float4*>(&p[t * 4]);

    float m = fmaxf(fmaxf(v.x, v.y), fmaxf(v.z, v.w));
#pragma unroll
    for (int o = 16; o > 0; o >>= 1) m = fmaxf(m, __shfl_xor_sync(0xffffffffu, m, o));
    __shared__ float sm[4];
    if (lane == 0) sm[w] = m;
    __syncthreads();
    m = fmaxf(fmaxf(sm[0], sm[1]), fmaxf(sm[2], sm[3]));

    v.x = __expf(v.x - m); v.y = __expf(v.y - m);
    v.z = __expf(v.z - m); v.w = __expf(v.w - m);
    float s = v.x + v.y + v.z + v.w;
#pragma unroll
    for (int o = 16; o > 0; o >>= 1) s += __shfl_xor_sync(0xffffffffu, s, o);
    __shared__ float ss[4];
    if (lane == 0) ss[w] = s;
    __syncthreads();
    s = ss[0] + ss[1] + ss[2] + ss[3];

    float inv = 1.0f / s;
    v.x *= inv; v.y *= inv; v.z *= inv; v.w *= inv;
    *reinterpret_cast<float4*>(&p[t * 4]) = v;
}

// ---------------------------------------------------------------------------
// Phase 4: out[b][r][d] = sum_x attn[b][r][x] * X[b][x][d]   (fp32 NN GEMM)
// ---------------------------------------------------------------------------
__global__ __launch_bounds__(256) void out_gemm_kernel(const float* __restrict__ X,
                                                       float* __restrict__ out) {
    __shared__ float As[32][64];   // [k][m=r]
    __shared__ float Bs[32][64];   // [k][n=d]
    int tid = threadIdx.x;
    int tx = tid & 15, ty = tid >> 4;
    int n0 = blockIdx.x * 64, m0 = blockIdx.y * 64, b = blockIdx.z;
    const float* Ab = g_S + (size_t)b * NR_ * NX_;
    const float* Xb = X + (size_t)b * NX_ * D_;

    float acc[4][4] = {};

    for (int k0 = 0; k0 < NX_; k0 += 32) {
#pragma unroll
        for (int l = 0; l < 2; l++) {
            int f = tid + l * 256;
            int row = f >> 3, c4 = f & 7;
            float4 v = *reinterpret_cast<const float4*>(&Ab[(size_t)(m0 + row) * NX_ + k0 + c4 * 4]);
            As[c4 * 4 + 0][row] = v.x; As[c4 * 4 + 1][row] = v.y;
            As[c4 * 4 + 2][row] = v.z; As[c4 * 4 + 3][row] = v.w;
        }
#pragma unroll
        for (int l = 0; l < 2; l++) {
            int f = tid + l * 256;
            int row = f >> 4, c4 = f & 15;
            float4 v = *reinterpret_cast<const float4*>(&Xb[(size_t)(k0 + row) * D_ + n0 + c4 * 4]);
            *reinterpret_cast<float4*>(&Bs[row][c4 * 4]) = v;
        }
        __syncthreads();
#pragma unroll
        for (int k = 0; k < 32; k++) {
            float4 a4 = *reinterpret_cast<const float4*>(&As[k][ty * 4]);
            float4 b4 = *reinterpret_cast<const float4*>(&Bs[k][tx * 4]);
            float a[4] = {a4.x, a4.y, a4.z, a4.w};
            float bb[4] = {b4.x, b4.y, b4.z, b4.w};
#pragma unroll
            for (int i = 0; i < 4; i++)
#pragma unroll
                for (int j = 0; j < 4; j++)
                    acc[i][j] += a[i] * bb[j];
        }
        __syncthreads();
    }

#pragma unroll
    for (int i = 0; i < 4; i++) {
        float4 o = {acc[i][0], acc[i][1], acc[i][2], acc[i][3]};
        *reinterpret_cast<float4*>(&out[((size_t)b * NR_ + m0 + ty * 4 + i) * D_ + n0 + tx * 4]) = o;
    }
}

// ---------------------------------------------------------------------------
// Launch (graph-capturable, allocation-free).
// Inputs: X, ref, W_X, b_X, W_ref, b_ref, v_w, v_b (v_b drops out of softmax).
// ---------------------------------------------------------------------------
extern "C" void kernel_launch(void* const* d_in, const int* in_sizes, int n_in,
                              void* d_out, int out_size) {
    const float* X     = (const float*)d_in[0];
    const float* ref   = (const float*)d_in[1];
    const float* W_X   = (const float*)d_in[2];
    const float* b_X   = (const float*)d_in[3];
    const float* W_ref = (const float*)d_in[4];
    const float* b_ref = (const float*)d_in[5];
    const float* v_w   = (const float*)d_in[6];
    float* out = (float*)d_out;

    dim3 blk(256);
    proj_kernel<<<dim3(NX_ / 64, H_ / 64, B_), blk>>>(X,   W_X,   b_X,   0);
    proj_kernel<<<dim3(NR_ / 64, H_ / 64, B_), blk>>>(ref, W_ref, b_ref, 1);
    score_kernel<<<dim3(NX_ / 64, NR_ / 64, B_), blk>>>(v_w);
    softmax512_kernel<<<B_ * NR_, 128>>>();
    out_gemm_kernel<<<dim3(D_ / 64, NR_ / 64, B_), blk>>>(X, out);
}

// round 6
// speedup vs baseline: 1.0523x; 1.0042x over previous
#include <cuda_runtime.h>
#include <cuda_fp16.h>

// Problem constants
#define B_   8
#define NX_  512
#define NR_  512
#define D_   256
#define H_   256

// Scratch (device globals — no allocation allowed anywhere)
__device__ __half g_hXT[B_ * H_ * NX_];   // [b][h][x]  fp16, transposed
__device__ __half g_hRT[B_ * H_ * NR_];   // [b][h][r]  fp16, transposed
__device__ float  g_S  [B_ * NR_ * NX_];  // [b][r][x]  scores -> attn in place

__device__ __forceinline__ __half2 tanh2(__half2 x) {
    __half2 y;
    asm("tanh.approx.f16x2 %0, %1;"
        : "=r"(*reinterpret_cast<unsigned*>(&y))
        : "r"(*reinterpret_cast<unsigned*>(&x)));
    return y;
}

// ---------------------------------------------------------------------------
// Phase 1: hT[b][h][x] = sum_d W[h][d] * A[b][x][d] + bias[h], stored fp16.
// M-dim = h (64-tile), N-dim = x (64-tile), K = D, fp32 compute.
// ---------------------------------------------------------------------------
__global__ __launch_bounds__(256) void proj_kernel(const float* __restrict__ A,
                                                   const float* __restrict__ W,
                                                   const float* __restrict__ bias,
                                                   int which) {
    __shared__ float Ws[32][64];   // [k][h]
    __shared__ float As[32][64];   // [k][x]
    __half* C = which ? g_hRT : g_hXT;
    const int K = D_;
    int tid = threadIdx.x;
    int tx = tid & 15, ty = tid >> 4;
    int x0 = blockIdx.x * 64, h0 = blockIdx.y * 64, b = blockIdx.z;
    const float* Ab = A + (size_t)b * NX_ * D_;   // NX_ == NR_

    float acc[4][4] = {};

    for (int k0 = 0; k0 < K; k0 += 32) {
#pragma unroll
        for (int l = 0; l < 2; l++) {
            int f = tid + l * 256;
            int row = f >> 3, c4 = f & 7;
            float4 w = *reinterpret_cast<const float4*>(&W[(size_t)(h0 + row) * K + k0 + c4 * 4]);
            Ws[c4 * 4 + 0][row] = w.x; Ws[c4 * 4 + 1][row] = w.y;
            Ws[c4 * 4 + 2][row] = w.z; Ws[c4 * 4 + 3][row] = w.w;
            float4 v = *reinterpret_cast<const float4*>(&Ab[(size_t)(x0 + row) * K + k0 + c4 * 4]);
            As[c4 * 4 + 0][row] = v.x; As[c4 * 4 + 1][row] = v.y;
            As[c4 * 4 + 2][row] = v.z; As[c4 * 4 + 3][row] = v.w;
        }
        __syncthreads();
#pragma unroll
        for (int k = 0; k < 32; k++) {
            float4 a4 = *reinterpret_cast<const float4*>(&Ws[k][ty * 4]);   // h
            float4 b4 = *reinterpret_cast<const float4*>(&As[k][tx * 4]);   // x
            float a[4] = {a4.x, a4.y, a4.z, a4.w};
            float bb[4] = {b4.x, b4.y, b4.z, b4.w};
#pragma unroll
            for (int i = 0; i < 4; i++)
#pragma unroll
                for (int j = 0; j < 4; j++)
                    acc[i][j] += a[i] * bb[j];
        }
        __syncthreads();
    }

#pragma unroll
    for (int i = 0; i < 4; i++) {
        int h = h0 + ty * 4 + i;
        float bb = bias[h];
        __half2 p0 = __floats2half2_rn(acc[i][0] + bb, acc[i][1] + bb);
        __half2 p1 = __floats2half2_rn(acc[i][2] + bb, acc[i][3] + bb);
        uint2 pk = {*reinterpret_cast<unsigned*>(&p0), *reinterpret_cast<unsigned*>(&p1)};
        *reinterpret_cast<uint2*>(&C[((size_t)b * H_ + h) * NX_ + x0 + tx * 4]) = pk;
    }
}

// ---------------------------------------------------------------------------
// Phase 2: S[b][r][x] = sum_h v[h] * tanh(hX[b][h][x] + hR[b][h][r])
// f16x2 tanh pairs along x (halves MUFU count), HFMA2 accumulation in half2
// over 8-h chunks, flushed into fp32 accumulators (F2F count reduced 8x).
// v_b / constants dropped (softmax shift-invariant along x).
// ---------------------------------------------------------------------------
__global__ __launch_bounds__(256) void score_kernel(const float* __restrict__ vw) {
    __shared__ __half  sX[32][64];   // [h][x]
    __shared__ __half  sR[32][64];   // [h][r]
    __shared__ __half2 sv2[32];      // v[h] broadcast pair
    int tid = threadIdx.x;
    int tx = tid & 15, ty = tid >> 4;
    int x0 = blockIdx.x * 64, r0 = blockIdx.y * 64, b = blockIdx.z;
    const __half* hXb = g_hXT + (size_t)b * H_ * NX_;
    const __half* hRb = g_hRT + (size_t)b * H_ * NR_;

    float acc[4][4] = {};

    for (int h0 = 0; h0 < H_; h0 += 32) {
        {
            int row = tid >> 3, seg = tid & 7;
            *reinterpret_cast<uint4*>(&sX[row][seg * 8]) =
                *reinterpret_cast<const uint4*>(&hXb[(size_t)(h0 + row) * NX_ + x0 + seg * 8]);
            *reinterpret_cast<uint4*>(&sR[row][seg * 8]) =
                *reinterpret_cast<const uint4*>(&hRb[(size_t)(h0 + row) * NR_ + r0 + seg * 8]);
            if (tid < 32) sv2[tid] = __half2half2(__float2half_rn(vw[h0 + tid]));
        }
        __syncthreads();

#pragma unroll
        for (int hh = 0; hh < 32; hh += 8) {
            __half2 acc2[4][2] = {};
#pragma unroll
            for (int h = 0; h < 8; h++) {
                int hc = hh + h;
                __half2 v2 = sv2[hc];
                uint2 xu = *reinterpret_cast<const uint2*>(&sX[hc][tx * 4]);
                uint2 ru = *reinterpret_cast<const uint2*>(&sR[hc][ty * 4]);
                __half2 x2[2] = {*reinterpret_cast<__half2*>(&xu.x),
                                 *reinterpret_cast<__half2*>(&xu.y)};
                __half2 ra = *reinterpret_cast<__half2*>(&ru.x);
                __half2 rb = *reinterpret_cast<__half2*>(&ru.y);
                __half2 r2[4] = {__half2half2(__low2half(ra)), __half2half2(__high2half(ra)),
                                 __half2half2(__low2half(rb)), __half2half2(__high2half(rb))};
#pragma unroll
                for (int i = 0; i < 4; i++)
#pragma unroll
                    for (int j2 = 0; j2 < 2; j2++) {
                        __half2 t = tanh2(__hadd2(r2[i], x2[j2]));
                        acc2[i][j2] = __hfma2(v2, t, acc2[i][j2]);
                    }
            }
            // flush half2 partials into fp32 accumulators
#pragma unroll
            for (int i = 0; i < 4; i++)
#pragma unroll
                for (int j2 = 0; j2 < 2; j2++) {
                    float2 f = __half22float2(acc2[i][j2]);
                    acc[i][2 * j2 + 0] += f.x;
                    acc[i][2 * j2 + 1] += f.y;
                }
        }
        __syncthreads();
    }

    float* Sb = g_S + (size_t)b * NR_ * NX_;
#pragma unroll
    for (int i = 0; i < 4; i++) {
        float4 o = {acc[i][0], acc[i][1], acc[i][2], acc[i][3]};
        *reinterpret_cast<float4*>(&Sb[(size_t)(r0 + ty * 4 + i) * NX_ + x0 + tx * 4]) = o;
    }
}

// ---------------------------------------------------------------------------
// Phase 3: row-wise softmax over 512 x-values of each S[b][r][:] (in place)
// ---------------------------------------------------------------------------
__global__ __launch_bounds__(128) void softmax512_kernel() {
    int row = blockIdx.x;
    float* p = g_S + (size_t)row * NX_;
    int t = threadIdx.x;
    int w = t >> 5, lane = t & 31;

    float4 v = *reinterpret_cast<float4*>(&p[t * 4]);

    float m = fmaxf(fmaxf(v.x, v.y), fmaxf(v.z, v.w));
#pragma unroll
    for (int o = 16; o > 0; o >>= 1) m = fmaxf(m, __shfl_xor_sync(0xffffffffu, m, o));
    __shared__ float sm[4];
    if (lane == 0) sm[w] = m;
    __syncthreads();
    m = fmaxf(fmaxf(sm[0], sm[1]), fmaxf(sm[2], sm[3]));

    v.x = __expf(v.x - m); v.y = __expf(v.y - m);
    v.z = __expf(v.z - m); v.w = __expf(v.w - m);
    float s = v.x + v.y + v.z + v.w;
#pragma unroll
    for (int o = 16; o > 0; o >>= 1) s += __shfl_xor_sync(0xffffffffu, s, o);
    __shared__ float ss[4];
    if (lane == 0) ss[w] = s;
    __syncthreads();
    s = ss[0] + ss[1] + ss[2] + ss[3];

    float inv = 1.0f / s;
    v.x *= inv; v.y *= inv; v.z *= inv; v.w *= inv;
    *reinterpret_cast<float4*>(&p[t * 4]) = v;
}

// ---------------------------------------------------------------------------
// Phase 4: out[b][r][d] = sum_x attn[b][r][x] * X[b][x][d]   (fp32 NN GEMM)
// ---------------------------------------------------------------------------
__global__ __launch_bounds__(256) void out_gemm_kernel(const float* __restrict__ X,
                                                       float* __restrict__ out) {
    __shared__ float As[32][64];   // [k][m=r]
    __shared__ float Bs[32][64];   // [k][n=d]
    int tid = threadIdx.x;
    int tx = tid & 15, ty = tid >> 4;
    int n0 = blockIdx.x * 64, m0 = blockIdx.y * 64, b = blockIdx.z;
    const float* Ab = g_S + (size_t)b * NR_ * NX_;
    const float* Xb = X + (size_t)b * NX_ * D_;

    float acc[4][4] = {};

    for (int k0 = 0; k0 < NX_; k0 += 32) {
#pragma unroll
        for (int l = 0; l < 2; l++) {
            int f = tid + l * 256;
            int row = f >> 3, c4 = f & 7;
            float4 v = *reinterpret_cast<const float4*>(&Ab[(size_t)(m0 + row) * NX_ + k0 + c4 * 4]);
            As[c4 * 4 + 0][row] = v.x; As[c4 * 4 + 1][row] = v.y;
            As[c4 * 4 + 2][row] = v.z; As[c4 * 4 + 3][row] = v.w;
        }
#pragma unroll
        for (int l = 0; l < 2; l++) {
            int f = tid + l * 256;
            int row = f >> 4, c4 = f & 15;
            float4 v = *reinterpret_cast<const float4*>(&Xb[(size_t)(k0 + row) * D_ + n0 + c4 * 4]);
            *reinterpret_cast<float4*>(&Bs[row][c4 * 4]) = v;
        }
        __syncthreads();
#pragma unroll
        for (int k = 0; k < 32; k++) {
            float4 a4 = *reinterpret_cast<const float4*>(&As[k][ty * 4]);
            float4 b4 = *reinterpret_cast<const float4*>(&Bs[k][tx * 4]);
            float a[4] = {a4.x, a4.y, a4.z, a4.w};
            float bb[4] = {b4.x, b4.y, b4.z, b4.w};
#pragma unroll
            for (int i = 0; i < 4; i++)
#pragma unroll
                for (int j = 0; j < 4; j++)
                    acc[i][j] += a[i] * bb[j];
        }
        __syncthreads();
    }

#pragma unroll
    for (int i = 0; i < 4; i++) {
        float4 o = {acc[i][0], acc[i][1], acc[i][2], acc[i][3]};
        *reinterpret_cast<float4*>(&out[((size_t)b * NR_ + m0 + ty * 4 + i) * D_ + n0 + tx * 4]) = o;
    }
}

// ---------------------------------------------------------------------------
// Launch (graph-capturable, allocation-free).
// Inputs: X, ref, W_X, b_X, W_ref, b_ref, v_w, v_b (v_b drops out of softmax).
// ---------------------------------------------------------------------------
extern "C" void kernel_launch(void* const* d_in, const int* in_sizes, int n_in,
                              void* d_out, int out_size) {
    const float* X     = (const float*)d_in[0];
    const float* ref   = (const float*)d_in[1];
    const float* W_X   = (const float*)d_in[2];
    const float* b_X   = (const float*)d_in[3];
    const float* W_ref = (const float*)d_in[4];
    const float* b_ref = (const float*)d_in[5];
    const float* v_w   = (const float*)d_in[6];
    float* out = (float*)d_out;

    dim3 blk(256);
    proj_kernel<<<dim3(NX_ / 64, H_ / 64, B_), blk>>>(X,   W_X,   b_X,   0);
    proj_kernel<<<dim3(NR_ / 64, H_ / 64, B_), blk>>>(ref, W_ref, b_ref, 1);
    score_kernel<<<dim3(NX_ / 64, NR_ / 64, B_), blk>>>(v_w);
    softmax512_kernel<<<B_ * NR_, 128>>>();
    out_gemm_kernel<<<dim3(D_ / 64, NR_ / 64, B_), blk>>>(X, out);
}

// round 7
// speedup vs baseline: 1.0598x; 1.0072x over previous
#include <cuda_runtime.h>
#include <cuda_fp16.h>

#define B_   8
#define NX_  512
#define NR_  512
#define D_   256
#define H_   256

// Scratch (device globals — no allocation allowed anywhere)
__device__ __half   g_hXT[B_ * H_ * NX_];   // [b][h][x]  fp16, transposed
__device__ __half   g_hRT[B_ * H_ * NR_];   // [b][h][r]  fp16, transposed
__device__ float    g_S  [B_ * NR_ * NX_];  // [b][r][x]  scores -> attn in place
__device__ unsigned g_tile;                 // dynamic tile counter for score

__device__ __forceinline__ __half2 tanh2(__half2 x) {
    __half2 y;
    asm("tanh.approx.f16x2 %0, %1;"
        : "=r"(*reinterpret_cast<unsigned*>(&y))
        : "r"(*reinterpret_cast<unsigned*>(&x)));
    return y;
}

// ---------------------------------------------------------------------------
// Phase 1 (merged): hT[b][h][x] = sum_d W[h][d]*A[b][x][d] + bias[h], fp16 out.
// grid.z in [0,16): z<8 -> X/W_X/b_X -> g_hXT ; z>=8 -> ref/W_ref/b_ref -> g_hRT
// Block (0,0,0) thread 0 also resets the score tile counter (stream-ordered).
// ---------------------------------------------------------------------------
__global__ __launch_bounds__(256) void proj_kernel(const float* __restrict__ X,
                                                   const float* __restrict__ ref,
                                                   const float* __restrict__ W_X,
                                                   const float* __restrict__ b_X,
                                                   const float* __restrict__ W_ref,
                                                   const float* __restrict__ b_ref) {
    __shared__ float Ws[32][64];   // [k][h]
    __shared__ float As[32][64];   // [k][x]
    int tid = threadIdx.x;
    if (blockIdx.x == 0 && blockIdx.y == 0 && blockIdx.z == 0 && tid == 0)
        g_tile = 0u;

    int z = blockIdx.z;
    int b = z & 7;
    const float* A    = (z < 8) ? X     : ref;
    const float* W    = (z < 8) ? W_X   : W_ref;
    const float* bias = (z < 8) ? b_X   : b_ref;
    __half*      C    = (z < 8) ? g_hXT : g_hRT;

    const int K = D_;
    int tx = tid & 15, ty = tid >> 4;
    int x0 = blockIdx.x * 64, h0 = blockIdx.y * 64;
    const float* Ab = A + (size_t)b * NX_ * D_;

    float acc[4][4] = {};

    for (int k0 = 0; k0 < K; k0 += 32) {
#pragma unroll
        for (int l = 0; l < 2; l++) {
            int f = tid + l * 256;
            int row = f >> 3, c4 = f & 7;
            float4 w = *reinterpret_cast<const float4*>(&W[(size_t)(h0 + row) * K + k0 + c4 * 4]);
            Ws[c4 * 4 + 0][row] = w.x; Ws[c4 * 4 + 1][row] = w.y;
            Ws[c4 * 4 + 2][row] = w.z; Ws[c4 * 4 + 3][row] = w.w;
            float4 v = *reinterpret_cast<const float4*>(&Ab[(size_t)(x0 + row) * K + k0 + c4 * 4]);
            As[c4 * 4 + 0][row] = v.x; As[c4 * 4 + 1][row] = v.y;
            As[c4 * 4 + 2][row] = v.z; As[c4 * 4 + 3][row] = v.w;
        }
        __syncthreads();
#pragma unroll
        for (int k = 0; k < 32; k++) {
            float4 a4 = *reinterpret_cast<const float4*>(&Ws[k][ty * 4]);
            float4 b4 = *reinterpret_cast<const float4*>(&As[k][tx * 4]);
            float a[4] = {a4.x, a4.y, a4.z, a4.w};
            float bb[4] = {b4.x, b4.y, b4.z, b4.w};
#pragma unroll
            for (int i = 0; i < 4; i++)
#pragma unroll
                for (int j = 0; j < 4; j++)
                    acc[i][j] += a[i] * bb[j];
        }
        __syncthreads();
    }

#pragma unroll
    for (int i = 0; i < 4; i++) {
        int h = h0 + ty * 4 + i;
        float bb = bias[h];
        __half2 p0 = __floats2half2_rn(acc[i][0] + bb, acc[i][1] + bb);
        __half2 p1 = __floats2half2_rn(acc[i][2] + bb, acc[i][3] + bb);
        uint2 pk = {*reinterpret_cast<unsigned*>(&p0), *reinterpret_cast<unsigned*>(&p1)};
        *reinterpret_cast<uint2*>(&C[((size_t)b * H_ + h) * NX_ + x0 + tx * 4]) = pk;
    }
}

// ---------------------------------------------------------------------------
// Phase 2: S[b][r][x] = sum_h v[h]*tanh(hX[b][h][x] + hR[b][h][r])
// Persistent: 296 CTAs (2/SM), dynamic tile counter -> no wave tail.
// sR2 pre-broadcast ((r,r) half2 pairs) -> no PRMT in hot loop.
// HFMA2 accumulation over 8-h chunks, fp32 flush. v_b dropped (shift-invar).
// ---------------------------------------------------------------------------
#define NTILES      512   // 8 x-tiles * 8 r-tiles * 8 batches (64x64 tiles)
#define SCORE_CTAS  296

__global__ __launch_bounds__(256) void score_kernel(const float* __restrict__ vw) {
    __shared__ __half   sX [32][64];    // [h][x]            4 KB
    __shared__ __half2  sR2[32][64];    // [h][r] as (r,r)   8 KB
    __shared__ __half2  sv2[H_];        //                   1 KB
    __shared__ unsigned s_tile;

    int tid = threadIdx.x;
    int tx = tid & 15, ty = tid >> 4;
    int frow = tid >> 3, fseg = tid & 7;

    sv2[tid] = __half2half2(__float2half_rn(vw[tid]));   // 256 == H_

    for (;;) {
        __syncthreads();                       // protect s_tile reuse
        if (tid == 0) s_tile = atomicAdd(&g_tile, 1u);
        __syncthreads();
        unsigned t = s_tile;
        if (t >= NTILES) break;
        int b  = (int)(t >> 6);
        int r0 = (int)((t >> 3) & 7) * 64;
        int x0 = (int)(t & 7) * 64;
        const __half* hXb = g_hXT + (size_t)b * H_ * NX_;
        const __half* hRb = g_hRT + (size_t)b * H_ * NR_;

        float acc[4][4] = {};

        for (int h0 = 0; h0 < H_; h0 += 32) {
            *reinterpret_cast<uint4*>(&sX[frow][fseg * 8]) =
                *reinterpret_cast<const uint4*>(&hXb[(size_t)(h0 + frow) * NX_ + x0 + fseg * 8]);
            uint4 rv = *reinterpret_cast<const uint4*>(&hRb[(size_t)(h0 + frow) * NR_ + r0 + fseg * 8]);
            const __half* rh = reinterpret_cast<const __half*>(&rv);
            __half2* dst = &sR2[frow][fseg * 8];
#pragma unroll
            for (int k = 0; k < 8; k++) dst[k] = __half2half2(rh[k]);
            __syncthreads();

#pragma unroll
            for (int hh = 0; hh < 32; hh += 8) {
                __half2 a2[4][2] = {};
#pragma unroll
                for (int h = 0; h < 8; h++) {
                    int hc = hh + h;
                    __half2 v2 = sv2[h0 + hc];
                    uint2 xu = *reinterpret_cast<const uint2*>(&sX[hc][tx * 4]);
                    uint4 ru = *reinterpret_cast<const uint4*>(&sR2[hc][ty * 4]);
                    __half2 x2[2] = {*reinterpret_cast<__half2*>(&xu.x),
                                     *reinterpret_cast<__half2*>(&xu.y)};
                    __half2 r2[4] = {*reinterpret_cast<__half2*>(&ru.x),
                                     *reinterpret_cast<__half2*>(&ru.y),
                                     *reinterpret_cast<__half2*>(&ru.z),
                                     *reinterpret_cast<__half2*>(&ru.w)};
#pragma unroll
                    for (int i = 0; i < 4; i++)
#pragma unroll
                        for (int j2 = 0; j2 < 2; j2++)
                            a2[i][j2] = __hfma2(v2, tanh2(__hadd2(r2[i], x2[j2])), a2[i][j2]);
                }
#pragma unroll
                for (int i = 0; i < 4; i++)
#pragma unroll
                    for (int j2 = 0; j2 < 2; j2++) {
                        float2 f = __half22float2(a2[i][j2]);
                        acc[i][2 * j2 + 0] += f.x;
                        acc[i][2 * j2 + 1] += f.y;
                    }
            }
            __syncthreads();
        }

        float* Sb = g_S + (size_t)b * NR_ * NX_;
#pragma unroll
        for (int i = 0; i < 4; i++) {
            float4 o = {acc[i][0], acc[i][1], acc[i][2], acc[i][3]};
            *reinterpret_cast<float4*>(&Sb[(size_t)(r0 + ty * 4 + i) * NX_ + x0 + tx * 4]) = o;
        }
    }
}

// ---------------------------------------------------------------------------
// Phase 3: row-wise softmax over 512 x-values of each S[b][r][:] (in place)
// ---------------------------------------------------------------------------
__global__ __launch_bounds__(128) void softmax512_kernel() {
    int row = blockIdx.x;
    float* p = g_S + (size_t)row * NX_;
    int t = threadIdx.x;
    int w = t >> 5, lane = t & 31;

    float4 v = *reinterpret_cast<float4*>(&p[t * 4]);

    float m = fmaxf(fmaxf(v.x, v.y), fmaxf(v.z, v.w));
#pragma unroll
    for (int o = 16; o > 0; o >>= 1) m = fmaxf(m, __shfl_xor_sync(0xffffffffu, m, o));
    __shared__ float sm[4];
    if (lane == 0) sm[w] = m;
    __syncthreads();
    m = fmaxf(fmaxf(sm[0], sm[1]), fmaxf(sm[2], sm[3]));

    v.x = __expf(v.x - m); v.y = __expf(v.y - m);
    v.z = __expf(v.z - m); v.w = __expf(v.w - m);
    float s = v.x + v.y + v.z + v.w;
#pragma unroll
    for (int o = 16; o > 0; o >>= 1) s += __shfl_xor_sync(0xffffffffu, s, o);
    __shared__ float ss[4];
    if (lane == 0) ss[w] = s;
    __syncthreads();
    s = ss[0] + ss[1] + ss[2] + ss[3];

    float inv = 1.0f / s;
    v.x *= inv; v.y *= inv; v.z *= inv; v.w *= inv;
    *reinterpret_cast<float4*>(&p[t * 4]) = v;
}

// ---------------------------------------------------------------------------
// Phase 4: out[b][r][d] = sum_x attn[b][r][x] * X[b][x][d]   (fp32 NN GEMM)
// ---------------------------------------------------------------------------
__global__ __launch_bounds__(256) void out_gemm_kernel(const float* __restrict__ X,
                                                       float* __restrict__ out) {
    __shared__ float As[32][64];   // [k][m=r]
    __shared__ float Bs[32][64];   // [k][n=d]
    int tid = threadIdx.x;
    int tx = tid & 15, ty = tid >> 4;
    int n0 = blockIdx.x * 64, m0 = blockIdx.y * 64, b = blockIdx.z;
    const float* Ab = g_S + (size_t)b * NR_ * NX_;
    const float* Xb = X + (size_t)b * NX_ * D_;

    float acc[4][4] = {};

    for (int k0 = 0; k0 < NX_; k0 += 32) {
#pragma unroll
        for (int l = 0; l < 2; l++) {
            int f = tid + l * 256;
            int row = f >> 3, c4 = f & 7;
            float4 v = *reinterpret_cast<const float4*>(&Ab[(size_t)(m0 + row) * NX_ + k0 + c4 * 4]);
            As[c4 * 4 + 0][row] = v.x; As[c4 * 4 + 1][row] = v.y;
            As[c4 * 4 + 2][row] = v.z; As[c4 * 4 + 3][row] = v.w;
        }
#pragma unroll
        for (int l = 0; l < 2; l++) {
            int f = tid + l * 256;
            int row = f >> 4, c4 = f & 15;
            float4 v = *reinterpret_cast<const float4*>(&Xb[(size_t)(k0 + row) * D_ + n0 + c4 * 4]);
            *reinterpret_cast<float4*>(&Bs[row][c4 * 4]) = v;
        }
        __syncthreads();
#pragma unroll
        for (int k = 0; k < 32; k++) {
            float4 a4 = *reinterpret_cast<const float4*>(&As[k][ty * 4]);
            float4 b4 = *reinterpret_cast<const float4*>(&Bs[k][tx * 4]);
            float a[4] = {a4.x, a4.y, a4.z, a4.w};
            float bb[4] = {b4.x, b4.y, b4.z, b4.w};
#pragma unroll
            for (int i = 0; i < 4; i++)
#pragma unroll
                for (int j = 0; j < 4; j++)
                    acc[i][j] += a[i] * bb[j];
        }
        __syncthreads();
    }

#pragma unroll
    for (int i = 0; i < 4; i++) {
        float4 o = {acc[i][0], acc[i][1], acc[i][2], acc[i][3]};
        *reinterpret_cast<float4*>(&out[((size_t)b * NR_ + m0 + ty * 4 + i) * D_ + n0 + tx * 4]) = o;
    }
}

// ---------------------------------------------------------------------------
// Launch (graph-capturable, allocation-free).
// Inputs: X, ref, W_X, b_X, W_ref, b_ref, v_w, v_b (v_b drops out of softmax).
// ---------------------------------------------------------------------------
extern "C" void kernel_launch(void* const* d_in, const int* in_sizes, int n_in,
                              void* d_out, int out_size) {
    const float* X     = (const float*)d_in[0];
    const float* ref   = (const float*)d_in[1];
    const float* W_X   = (const float*)d_in[2];
    const float* b_X   = (const float*)d_in[3];
    const float* W_ref = (const float*)d_in[4];
    const float* b_ref = (const float*)d_in[5];
    const float* v_w   = (const float*)d_in[6];
    float* out = (float*)d_out;

    dim3 blk(256);
    proj_kernel<<<dim3(NX_ / 64, H_ / 64, 2 * B_), blk>>>(X, ref, W_X, b_X, W_ref, b_ref);
    score_kernel<<<SCORE_CTAS, blk>>>(v_w);
    softmax512_kernel<<<B_ * NR_, 128>>>();
    out_gemm_kernel<<<dim3(D_ / 64, NR_ / 64, B_), blk>>>(X, out);
}